// round 1
// baseline (speedup 1.0000x reference)
#include <cuda_runtime.h>
#include <cstdint>

// Problem constants (fixed shapes)
#define N_NODES 8192
#define N_EDGES 524288
#define D 256

// Scratch: projected features (24 MB total, L2-resident during edge phase)
__device__ float g_q[N_NODES * D];
__device__ float g_k[N_NODES * D];
__device__ float g_hp[N_NODES * D];

// ---------------------------------------------------------------------------
// Fused SGEMM: C = h @ {W | Wq | Wk}  (8192 x 768, K=256), bias on q/k parts.
// BM=128, BN=128, BK=16, 256 threads, 8x8 per thread.
// gridDim = (64, 6): blockIdx.y -> {0,1}=h_proj, {2,3}=q, {4,5}=k
// ---------------------------------------------------------------------------
__global__ __launch_bounds__(256) void gemm_qkp_kernel(
    const float* __restrict__ A,   // h [8192 x 256]
    const float* __restrict__ W,
    const float* __restrict__ Wq, const float* __restrict__ bq,
    const float* __restrict__ Wk, const float* __restrict__ bk)
{
    const int BM = 128, BN = 128, BK = 16, TM = 8, TN = 8;
    __shared__ float As[BK][BM];
    __shared__ float Bs[BK][BN];

    const int by  = blockIdx.y;
    const int mat = by >> 1;              // 0=h_proj, 1=q, 2=k
    const int n0  = (by & 1) * BN;        // column offset within the 256-wide matrix
    const int m0  = blockIdx.x * BM;

    const float* B    = (mat == 0) ? W   : (mat == 1) ? Wq : Wk;
    const float* bias = (mat == 1) ? bq  : (mat == 2) ? bk : nullptr;
    float* Cout       = (mat == 0) ? g_hp : (mat == 1) ? g_q : g_k;

    const int tid  = threadIdx.x;
    const int tcol = (tid & 15) * TN;     // 0..120
    const int trow = (tid >> 4) * TM;     // 0..120

    // A tile loads: 128 rows x 16 k. Each thread: 2 float4 (rows arow, arow+64).
    const int arow = tid >> 2;            // 0..63
    const int acol = (tid & 3) * 4;       // 0,4,8,12
    // B tile loads: 16 rows x 128 cols. Each thread: 2 float4 (rows brow, brow+8).
    const int brow = tid >> 5;            // 0..7
    const int bcol = (tid & 31) * 4;      // 0..124

    float acc[TM][TN] = {};

    for (int k0 = 0; k0 < D; k0 += BK) {
        float4 av0 = *(const float4*)&A[(size_t)(m0 + arow)      * D + k0 + acol];
        float4 av1 = *(const float4*)&A[(size_t)(m0 + arow + 64) * D + k0 + acol];
        As[acol + 0][arow] = av0.x; As[acol + 1][arow] = av0.y;
        As[acol + 2][arow] = av0.z; As[acol + 3][arow] = av0.w;
        As[acol + 0][arow + 64] = av1.x; As[acol + 1][arow + 64] = av1.y;
        As[acol + 2][arow + 64] = av1.z; As[acol + 3][arow + 64] = av1.w;

        float4 bv0 = *(const float4*)&B[(size_t)(k0 + brow)     * D + n0 + bcol];
        float4 bv1 = *(const float4*)&B[(size_t)(k0 + brow + 8) * D + n0 + bcol];
        *(float4*)&Bs[brow][bcol]     = bv0;
        *(float4*)&Bs[brow + 8][bcol] = bv1;

        __syncthreads();

        #pragma unroll
        for (int kk = 0; kk < BK; ++kk) {
            float ar[TM], br[TN];
            #pragma unroll
            for (int i = 0; i < TM; ++i) ar[i] = As[kk][trow + i];
            #pragma unroll
            for (int j = 0; j < TN; ++j) br[j] = Bs[kk][tcol + j];
            #pragma unroll
            for (int i = 0; i < TM; ++i)
                #pragma unroll
                for (int j = 0; j < TN; ++j)
                    acc[i][j] = fmaf(ar[i], br[j], acc[i][j]);
        }
        __syncthreads();
    }

    #pragma unroll
    for (int i = 0; i < TM; ++i) {
        const int m = m0 + trow + i;
        #pragma unroll
        for (int j = 0; j < TN; j += 4) {
            const int n = n0 + tcol + j;
            float4 v = make_float4(acc[i][j], acc[i][j+1], acc[i][j+2], acc[i][j+3]);
            if (bias) {
                v.x += bias[n];     v.y += bias[n + 1];
                v.z += bias[n + 2]; v.w += bias[n + 3];
            }
            *(float4*)&Cout[(size_t)m * D + n] = v;
        }
    }
}

// ---------------------------------------------------------------------------
// Zero d_out (float4)
// ---------------------------------------------------------------------------
__global__ void zero_kernel(float4* __restrict__ out, int n4)
{
    int i = blockIdx.x * blockDim.x + threadIdx.x;
    if (i < n4) out[i] = make_float4(0.f, 0.f, 0.f, 0.f);
}

// ---------------------------------------------------------------------------
// Edge kernel: 1 warp per edge.
//   a_e = dot(q[s], k[r]) (warp shuffle reduce)
//   out[r] += a_e * h_proj[s]   via red.global.add.v4.f32
// ---------------------------------------------------------------------------
__device__ __forceinline__ void red_add_v4(float* addr, float4 v)
{
    asm volatile("red.global.add.v4.f32 [%0], {%1, %2, %3, %4};"
                 :: "l"(addr), "f"(v.x), "f"(v.y), "f"(v.z), "f"(v.w)
                 : "memory");
}

__global__ __launch_bounds__(256) void edge_kernel(
    const int* __restrict__ senders,
    const int* __restrict__ receivers,
    float* __restrict__ out)
{
    const int warp = (blockIdx.x * blockDim.x + threadIdx.x) >> 5;
    const int lane = threadIdx.x & 31;
    if (warp >= N_EDGES) return;

    const int s = senders[warp];
    const int r = receivers[warp];

    const float4* qs = (const float4*)&g_q[(size_t)s * D];
    const float4* kr = (const float4*)&g_k[(size_t)r * D];

    const float4 q0 = qs[lane * 2], q1 = qs[lane * 2 + 1];
    const float4 k0 = kr[lane * 2], k1 = kr[lane * 2 + 1];

    float dot = q0.x * k0.x;
    dot = fmaf(q0.y, k0.y, dot);
    dot = fmaf(q0.z, k0.z, dot);
    dot = fmaf(q0.w, k0.w, dot);
    dot = fmaf(q1.x, k1.x, dot);
    dot = fmaf(q1.y, k1.y, dot);
    dot = fmaf(q1.z, k1.z, dot);
    dot = fmaf(q1.w, k1.w, dot);

    #pragma unroll
    for (int o = 16; o > 0; o >>= 1)
        dot += __shfl_xor_sync(0xffffffffu, dot, o);

    const float4* hp = (const float4*)&g_hp[(size_t)s * D];
    const float4 h0 = hp[lane * 2], h1 = hp[lane * 2 + 1];

    float* dst = &out[(size_t)r * D + lane * 8];
    red_add_v4(dst,     make_float4(h0.x * dot, h0.y * dot, h0.z * dot, h0.w * dot));
    red_add_v4(dst + 4, make_float4(h1.x * dot, h1.y * dot, h1.z * dot, h1.w * dot));
}

// ---------------------------------------------------------------------------
// In-place ReLU
// ---------------------------------------------------------------------------
__global__ void relu_kernel(float4* __restrict__ out, int n4)
{
    int i = blockIdx.x * blockDim.x + threadIdx.x;
    if (i < n4) {
        float4 v = out[i];
        v.x = fmaxf(v.x, 0.f); v.y = fmaxf(v.y, 0.f);
        v.z = fmaxf(v.z, 0.f); v.w = fmaxf(v.w, 0.f);
        out[i] = v;
    }
}

// ---------------------------------------------------------------------------
// Launch: inputs (metadata order): h, W, Wq, bq, Wk, bk, senders, receivers
// ---------------------------------------------------------------------------
extern "C" void kernel_launch(void* const* d_in, const int* in_sizes, int n_in,
                              void* d_out, int out_size)
{
    const float* h  = (const float*)d_in[0];
    const float* W  = (const float*)d_in[1];
    const float* Wq = (const float*)d_in[2];
    const float* bq = (const float*)d_in[3];
    const float* Wk = (const float*)d_in[4];
    const float* bk = (const float*)d_in[5];
    const int* senders   = (const int*)d_in[6];
    const int* receivers = (const int*)d_in[7];
    float* out = (float*)d_out;

    // 1) Fused projection GEMM: h_proj, q, k
    dim3 gemm_grid(N_NODES / 128, 6);
    gemm_qkp_kernel<<<gemm_grid, 256>>>(h, W, Wq, bq, Wk, bk);

    // 2) Zero output accumulator
    const int n4 = N_NODES * D / 4;  // 524288 float4
    zero_kernel<<<(n4 + 255) / 256, 256>>>((float4*)out, n4);

    // 3) Edge gather/scatter: 1 warp per edge, 8 warps per block
    edge_kernel<<<N_EDGES / 8, 256>>>(senders, receivers, out);

    // 4) ReLU in place
    relu_kernel<<<(n4 + 255) / 256, 256>>>((float4*)out, n4);
}

// round 3
// speedup vs baseline: 1.2621x; 1.2621x over previous
#include <cuda_runtime.h>
#include <cstdint>

#define N_NODES 8192
#define N_EDGES 524288
#define D 256

// Scratch (all __device__ globals — no allocation)
__device__ float g_q [N_NODES * D];
__device__ float g_k [N_NODES * D];
__device__ float g_hp[N_NODES * D];
__device__ int   g_count [N_NODES];
__device__ int   g_cursor[N_NODES];
__device__ int   g_offset[N_NODES + 1];
__device__ int   g_ss[N_EDGES];          // senders sorted by receiver

// ---------------------------------------------------------------------------
// Fused SGEMM: C = h @ {W | Wq | Wk}  (8192 x 768, K=256), bias on q/k parts.
// ---------------------------------------------------------------------------
__global__ __launch_bounds__(256) void gemm_qkp_kernel(
    const float* __restrict__ A,
    const float* __restrict__ W,
    const float* __restrict__ Wq, const float* __restrict__ bq,
    const float* __restrict__ Wk, const float* __restrict__ bk)
{
    const int BM = 128, BN = 128, BK = 16, TM = 8, TN = 8;
    __shared__ float As[BK][BM];
    __shared__ float Bs[BK][BN];

    const int by  = blockIdx.y;
    const int mat = by >> 1;
    const int n0  = (by & 1) * BN;
    const int m0  = blockIdx.x * BM;

    const float* B    = (mat == 0) ? W    : (mat == 1) ? Wq : Wk;
    const float* bias = (mat == 1) ? bq   : (mat == 2) ? bk : nullptr;
    float* Cout       = (mat == 0) ? g_hp : (mat == 1) ? g_q : g_k;

    const int tid  = threadIdx.x;
    const int tcol = (tid & 15) * TN;
    const int trow = (tid >> 4) * TM;

    const int arow = tid >> 2;
    const int acol = (tid & 3) * 4;
    const int brow = tid >> 5;
    const int bcol = (tid & 31) * 4;

    float acc[TM][TN] = {};

    for (int k0 = 0; k0 < D; k0 += BK) {
        float4 av0 = *(const float4*)&A[(size_t)(m0 + arow)      * D + k0 + acol];
        float4 av1 = *(const float4*)&A[(size_t)(m0 + arow + 64) * D + k0 + acol];
        As[acol + 0][arow] = av0.x; As[acol + 1][arow] = av0.y;
        As[acol + 2][arow] = av0.z; As[acol + 3][arow] = av0.w;
        As[acol + 0][arow + 64] = av1.x; As[acol + 1][arow + 64] = av1.y;
        As[acol + 2][arow + 64] = av1.z; As[acol + 3][arow + 64] = av1.w;

        float4 bv0 = *(const float4*)&B[(size_t)(k0 + brow)     * D + n0 + bcol];
        float4 bv1 = *(const float4*)&B[(size_t)(k0 + brow + 8) * D + n0 + bcol];
        *(float4*)&Bs[brow][bcol]     = bv0;
        *(float4*)&Bs[brow + 8][bcol] = bv1;

        __syncthreads();

        #pragma unroll
        for (int kk = 0; kk < BK; ++kk) {
            float ar[TM], br[TN];
            #pragma unroll
            for (int i = 0; i < TM; ++i) ar[i] = As[kk][trow + i];
            #pragma unroll
            for (int j = 0; j < TN; ++j) br[j] = Bs[kk][tcol + j];
            #pragma unroll
            for (int i = 0; i < TM; ++i)
                #pragma unroll
                for (int j = 0; j < TN; ++j)
                    acc[i][j] = fmaf(ar[i], br[j], acc[i][j]);
        }
        __syncthreads();
    }

    #pragma unroll
    for (int i = 0; i < TM; ++i) {
        const int m = m0 + trow + i;
        #pragma unroll
        for (int j = 0; j < TN; j += 4) {
            const int n = n0 + tcol + j;
            float4 v = make_float4(acc[i][j], acc[i][j+1], acc[i][j+2], acc[i][j+3]);
            if (bias) {
                v.x += bias[n];     v.y += bias[n + 1];
                v.z += bias[n + 2]; v.w += bias[n + 3];
            }
            *(float4*)&Cout[(size_t)m * D + n] = v;
        }
    }
}

// ---------------------------------------------------------------------------
// Counting sort of edges by receiver
// ---------------------------------------------------------------------------
__global__ void zero_counts_kernel()
{
    int i = blockIdx.x * blockDim.x + threadIdx.x;
    if (i < N_NODES) g_count[i] = 0;
}

__global__ void hist_kernel(const int* __restrict__ receivers)
{
    for (int e = blockIdx.x * blockDim.x + threadIdx.x; e < N_EDGES;
         e += gridDim.x * blockDim.x)
        atomicAdd(&g_count[receivers[e]], 1);
}

// Single-block scan over 8192 counts (1024 threads, 8 values each)
__global__ __launch_bounds__(1024) void scan_kernel()
{
    __shared__ int sm[1024];
    const int t = threadIdx.x;
    int v[8]; int sum = 0;
    #pragma unroll
    for (int i = 0; i < 8; ++i) { v[i] = g_count[t * 8 + i]; sum += v[i]; }
    sm[t] = sum;
    __syncthreads();
    #pragma unroll
    for (int off = 1; off < 1024; off <<= 1) {
        int x = (t >= off) ? sm[t - off] : 0;
        __syncthreads();
        sm[t] += x;
        __syncthreads();
    }
    int base = sm[t] - sum;   // exclusive prefix of this thread's 8-chunk
    if (t == 0) g_offset[0] = 0;
    #pragma unroll
    for (int i = 0; i < 8; ++i) {
        base += v[i];
        g_offset[t * 8 + i + 1] = base;   // inclusive -> offset[r+1]
        g_cursor[t * 8 + i] = 0;
    }
}

__global__ void scatter_kernel(const int* __restrict__ senders,
                               const int* __restrict__ receivers)
{
    for (int e = blockIdx.x * blockDim.x + threadIdx.x; e < N_EDGES;
         e += gridDim.x * blockDim.x) {
        const int r = receivers[e];
        const int pos = g_offset[r] + atomicAdd(&g_cursor[r], 1);
        g_ss[pos] = senders[e];
    }
}

// ---------------------------------------------------------------------------
// Gather/accumulate: 1 block (8 warps) per receiver. No atomics.
//   out[r] = relu( sum_{e in CSR[r]} (q[s_e] . k[r]) * hp[s_e] )
// ---------------------------------------------------------------------------
__global__ __launch_bounds__(256) void gather_kernel(float* __restrict__ out)
{
    const int r    = blockIdx.x;
    const int tid  = threadIdx.x;
    const int warp = tid >> 5;
    const int lane = tid & 31;

    __shared__ float ks[D];
    __shared__ float buf[8][D];   // per-warp partial output rows

    ks[tid] = g_k[(size_t)r * D + tid];
    __syncthreads();

    // Each lane owns dims [lane*8, lane*8+8)
    const float4 k0 = *(const float4*)&ks[lane * 8];
    const float4 k1 = *(const float4*)&ks[lane * 8 + 4];

    const int beg = g_offset[r];
    const int end = g_offset[r + 1];

    float4 acc0 = make_float4(0.f, 0.f, 0.f, 0.f);
    float4 acc1 = make_float4(0.f, 0.f, 0.f, 0.f);

    for (int e = beg + warp; e < end; e += 8) {
        const int s = g_ss[e];
        const float4* qs = (const float4*)&g_q[(size_t)s * D];
        const float4 q0 = qs[lane * 2], q1 = qs[lane * 2 + 1];

        float dot = q0.x * k0.x;
        dot = fmaf(q0.y, k0.y, dot);
        dot = fmaf(q0.z, k0.z, dot);
        dot = fmaf(q0.w, k0.w, dot);
        dot = fmaf(q1.x, k1.x, dot);
        dot = fmaf(q1.y, k1.y, dot);
        dot = fmaf(q1.z, k1.z, dot);
        dot = fmaf(q1.w, k1.w, dot);

        #pragma unroll
        for (int o = 16; o > 0; o >>= 1)
            dot += __shfl_xor_sync(0xffffffffu, dot, o);

        const float4* hp = (const float4*)&g_hp[(size_t)s * D];
        const float4 h0 = hp[lane * 2], h1 = hp[lane * 2 + 1];

        acc0.x = fmaf(dot, h0.x, acc0.x);
        acc0.y = fmaf(dot, h0.y, acc0.y);
        acc0.z = fmaf(dot, h0.z, acc0.z);
        acc0.w = fmaf(dot, h0.w, acc0.w);
        acc1.x = fmaf(dot, h1.x, acc1.x);
        acc1.y = fmaf(dot, h1.y, acc1.y);
        acc1.z = fmaf(dot, h1.z, acc1.z);
        acc1.w = fmaf(dot, h1.w, acc1.w);
    }

    *(float4*)&buf[warp][lane * 8]     = acc0;
    *(float4*)&buf[warp][lane * 8 + 4] = acc1;
    __syncthreads();

    // 256 threads: each reduces one dim across the 8 warp partials, relu, store
    float v = buf[0][tid];
    #pragma unroll
    for (int w = 1; w < 8; ++w) v += buf[w][tid];
    out[(size_t)r * D + tid] = fmaxf(v, 0.f);
}

// ---------------------------------------------------------------------------
// Launch: inputs: h, W, Wq, bq, Wk, bk, senders, receivers
// ---------------------------------------------------------------------------
extern "C" void kernel_launch(void* const* d_in, const int* in_sizes, int n_in,
                              void* d_out, int out_size)
{
    const float* h  = (const float*)d_in[0];
    const float* W  = (const float*)d_in[1];
    const float* Wq = (const float*)d_in[2];
    const float* bq = (const float*)d_in[3];
    const float* Wk = (const float*)d_in[4];
    const float* bk = (const float*)d_in[5];
    const int* senders   = (const int*)d_in[6];
    const int* receivers = (const int*)d_in[7];
    float* out = (float*)d_out;

    // 1) Projections (h_proj, q, k)
    dim3 gemm_grid(N_NODES / 128, 6);
    gemm_qkp_kernel<<<gemm_grid, 256>>>(h, W, Wq, bq, Wk, bk);

    // 2) Counting sort of edges by receiver
    zero_counts_kernel<<<N_NODES / 256, 256>>>();
    hist_kernel<<<512, 256>>>(receivers);
    scan_kernel<<<1, 1024>>>();
    scatter_kernel<<<512, 256>>>(senders, receivers);

    // 3) Per-receiver gather/accumulate with fused ReLU (writes every row)
    gather_kernel<<<N_NODES, 256>>>(out);
}

// round 5
// speedup vs baseline: 1.5503x; 1.2283x over previous
#include <cuda_runtime.h>
#include <cuda_bf16.h>
#include <cstdint>

#define N_NODES 8192
#define N_EDGES 524288
#define D 256

// ---------------- scratch (__device__ globals, no allocation) --------------
__device__ float g_q [N_NODES * D];
__device__ float g_k [N_NODES * D];
__device__ float g_hp[N_NODES * D];
__device__ int   g_count [N_NODES];
__device__ int   g_cursor[N_NODES];
__device__ int   g_offset[N_NODES + 1];
__device__ int   g_ss[N_EDGES];

__device__ __nv_bfloat16 g_ahi[N_NODES * D];   // h split-hi (row-major)
__device__ __nv_bfloat16 g_alo[N_NODES * D];   // h split-lo
__device__ __nv_bfloat16 g_wthi[3 * D * D];    // W^T split-hi: [mat][n][k]
__device__ __nv_bfloat16 g_wtlo[3 * D * D];    // W^T split-lo

// ---------------- split-precision conversion -------------------------------
__global__ __launch_bounds__(256) void convert_h_kernel(const float* __restrict__ h)
{
    const int i = blockIdx.x * blockDim.x + threadIdx.x;   // one float4 each
    float4 v = ((const float4*)h)[i];
    __nv_bfloat16 h0 = __float2bfloat16(v.x);
    __nv_bfloat16 h1 = __float2bfloat16(v.y);
    __nv_bfloat16 h2 = __float2bfloat16(v.z);
    __nv_bfloat16 h3 = __float2bfloat16(v.w);
    __nv_bfloat16 l0 = __float2bfloat16(v.x - __bfloat162float(h0));
    __nv_bfloat16 l1 = __float2bfloat16(v.y - __bfloat162float(h1));
    __nv_bfloat16 l2 = __float2bfloat16(v.z - __bfloat162float(h2));
    __nv_bfloat16 l3 = __float2bfloat16(v.w - __bfloat162float(h3));
    uint2 hw, lw;
    hw.x = (uint32_t)__bfloat16_as_ushort(h0) | ((uint32_t)__bfloat16_as_ushort(h1) << 16);
    hw.y = (uint32_t)__bfloat16_as_ushort(h2) | ((uint32_t)__bfloat16_as_ushort(h3) << 16);
    lw.x = (uint32_t)__bfloat16_as_ushort(l0) | ((uint32_t)__bfloat16_as_ushort(l1) << 16);
    lw.y = (uint32_t)__bfloat16_as_ushort(l2) | ((uint32_t)__bfloat16_as_ushort(l3) << 16);
    ((uint2*)g_ahi)[i] = hw;
    ((uint2*)g_alo)[i] = lw;
}

// W [k][n] fp32 -> Wt[mat][n][k] bf16 hi/lo (transposed so k is contiguous)
__global__ __launch_bounds__(256) void convert_w_kernel(
    const float* __restrict__ W, const float* __restrict__ Wq,
    const float* __restrict__ Wk)
{
    const int k   = blockIdx.x;
    const int mat = blockIdx.y;
    const int n   = threadIdx.x;
    const float* src = (mat == 0) ? W : (mat == 1) ? Wq : Wk;
    const float x = src[k * D + n];
    __nv_bfloat16 hi = __float2bfloat16(x);
    __nv_bfloat16 lo = __float2bfloat16(x - __bfloat162float(hi));
    g_wthi[mat * D * D + n * D + k] = hi;
    g_wtlo[mat * D * D + n * D + k] = lo;
}

// ---------------- split-bf16 HMMA GEMM -------------------------------------
// C = A @ B^T with A=hi+lo, B=hi+lo; acc += ahi*bhi + ahi*blo + alo*bhi (fp32)
// Block tile 128x128, BK=32. 8 warps in 4(m) x 2(n); warp tile 32x64.
#define BM 128
#define BN 128
#define BK 32
#define PAD 8
#define LDS_STRIDE (BK + PAD)   // 40 bf16 = 80 bytes, conflict-free

__device__ __forceinline__ void mma_bf16(float* c, const uint32_t* a, const uint32_t* b)
{
    asm volatile(
        "mma.sync.aligned.m16n8k16.row.col.f32.bf16.bf16.f32 "
        "{%0,%1,%2,%3}, {%4,%5,%6,%7}, {%8,%9}, {%0,%1,%2,%3};"
        : "+f"(c[0]), "+f"(c[1]), "+f"(c[2]), "+f"(c[3])
        : "r"(a[0]), "r"(a[1]), "r"(a[2]), "r"(a[3]), "r"(b[0]), "r"(b[1]));
}

__global__ __launch_bounds__(256) void hmma_kernel(const float* __restrict__ bq,
                                                   const float* __restrict__ bk)
{
    __shared__ __nv_bfloat16 Ahi[BM][LDS_STRIDE];
    __shared__ __nv_bfloat16 Alo[BM][LDS_STRIDE];
    __shared__ __nv_bfloat16 Bhi[BN][LDS_STRIDE];
    __shared__ __nv_bfloat16 Blo[BN][LDS_STRIDE];

    const int tid  = threadIdx.x;
    const int wid  = tid >> 5;
    const int lane = tid & 31;
    const int gid  = lane >> 2;        // group id 0..7
    const int tig  = lane & 3;         // thread in group

    const int wm = wid & 3;            // warp m 0..3  (32 rows each)
    const int wn = wid >> 2;           // warp n 0..1  (64 cols each)

    const int m0  = blockIdx.x * BM;
    const int mat = blockIdx.y >> 1;
    const int n0  = (blockIdx.y & 1) * BN;

    const __nv_bfloat16* Bh = g_wthi + mat * D * D;
    const __nv_bfloat16* Bl = g_wtlo + mat * D * D;
    float* Cout       = (mat == 0) ? g_hp : (mat == 1) ? g_q : g_k;
    const float* bias = (mat == 1) ? bq   : (mat == 2) ? bk : nullptr;

    float acc[2][8][4] = {};

    for (int k0 = 0; k0 < D; k0 += BK) {
        // ---- load tiles: 128x32 bf16 = 512 uint4 per matrix, 2 per thread --
        #pragma unroll
        for (int t = 0; t < 2; ++t) {
            const int idx = tid + t * 256;
            const int row = idx >> 2, cq = idx & 3;
            const size_t asrc = (size_t)(m0 + row) * D + k0 + cq * 8;
            const size_t bsrc = (size_t)(n0 + row) * D + k0 + cq * 8;
            *(uint4*)&Ahi[row][cq * 8] = *(const uint4*)(g_ahi + asrc);
            *(uint4*)&Alo[row][cq * 8] = *(const uint4*)(g_alo + asrc);
            *(uint4*)&Bhi[row][cq * 8] = *(const uint4*)(Bh + bsrc);
            *(uint4*)&Blo[row][cq * 8] = *(const uint4*)(Bl + bsrc);
        }
        __syncthreads();

        #pragma unroll
        for (int ks = 0; ks < BK / 16; ++ks) {
            const int kc = ks * 16 + tig * 2;

            uint32_t ah[2][4], al[2][4], bh[8][2], bl[8][2];
            #pragma unroll
            for (int i = 0; i < 2; ++i) {
                const int r = wm * 32 + i * 16 + gid;
                ah[i][0] = *(const uint32_t*)&Ahi[r][kc];
                ah[i][1] = *(const uint32_t*)&Ahi[r + 8][kc];
                ah[i][2] = *(const uint32_t*)&Ahi[r][kc + 8];
                ah[i][3] = *(const uint32_t*)&Ahi[r + 8][kc + 8];
                al[i][0] = *(const uint32_t*)&Alo[r][kc];
                al[i][1] = *(const uint32_t*)&Alo[r + 8][kc];
                al[i][2] = *(const uint32_t*)&Alo[r][kc + 8];
                al[i][3] = *(const uint32_t*)&Alo[r + 8][kc + 8];
            }
            #pragma unroll
            for (int j = 0; j < 8; ++j) {
                const int n = wn * 64 + j * 8 + gid;
                bh[j][0] = *(const uint32_t*)&Bhi[n][kc];
                bh[j][1] = *(const uint32_t*)&Bhi[n][kc + 8];
                bl[j][0] = *(const uint32_t*)&Blo[n][kc];
                bl[j][1] = *(const uint32_t*)&Blo[n][kc + 8];
            }

            #pragma unroll
            for (int i = 0; i < 2; ++i)
                #pragma unroll
                for (int j = 0; j < 8; ++j) {
                    mma_bf16(acc[i][j], ah[i], bh[j]);   // hi * hi
                    mma_bf16(acc[i][j], ah[i], bl[j]);   // hi * lo
                    mma_bf16(acc[i][j], al[i], bh[j]);   // lo * hi
                }
        }
        __syncthreads();
    }

    // ---- epilogue: bias + store (float2 per half-frag) ---------------------
    #pragma unroll
    for (int i = 0; i < 2; ++i) {
        const int row = m0 + wm * 32 + i * 16 + gid;
        #pragma unroll
        for (int j = 0; j < 8; ++j) {
            const int col = n0 + wn * 64 + j * 8 + tig * 2;
            float b0 = 0.f, b1 = 0.f;
            if (bias) { b0 = bias[col]; b1 = bias[col + 1]; }
            float2 v0 = make_float2(acc[i][j][0] + b0, acc[i][j][1] + b1);
            float2 v1 = make_float2(acc[i][j][2] + b0, acc[i][j][3] + b1);
            *(float2*)&Cout[(size_t)row * D + col]       = v0;
            *(float2*)&Cout[(size_t)(row + 8) * D + col] = v1;
        }
    }
}

// ---------------- counting sort by receiver --------------------------------
__global__ void zero_counts_kernel()
{
    int i = blockIdx.x * blockDim.x + threadIdx.x;
    if (i < N_NODES) g_count[i] = 0;
}

__global__ void hist_kernel(const int* __restrict__ receivers)
{
    for (int e = blockIdx.x * blockDim.x + threadIdx.x; e < N_EDGES;
         e += gridDim.x * blockDim.x)
        atomicAdd(&g_count[receivers[e]], 1);
}

// warp-shuffle scan: 1024 threads x 8 counts, 2 barriers
__global__ __launch_bounds__(1024) void scan_kernel()
{
    __shared__ int wsum[32];
    const int t = threadIdx.x, lane = t & 31, warp = t >> 5;
    int v[8]; int sum = 0;
    #pragma unroll
    for (int i = 0; i < 8; ++i) { v[i] = g_count[t * 8 + i]; sum += v[i]; }

    int s = sum;
    #pragma unroll
    for (int off = 1; off < 32; off <<= 1) {
        int x = __shfl_up_sync(0xffffffffu, s, off);
        if (lane >= off) s += x;
    }
    if (lane == 31) wsum[warp] = s;
    __syncthreads();
    if (warp == 0) {
        int ws = wsum[lane];
        #pragma unroll
        for (int off = 1; off < 32; off <<= 1) {
            int x = __shfl_up_sync(0xffffffffu, ws, off);
            if (lane >= off) ws += x;
        }
        wsum[lane] = ws;
    }
    __syncthreads();

    int base = s - sum + (warp ? wsum[warp - 1] : 0);   // exclusive prefix
    if (t == 0) g_offset[0] = 0;
    #pragma unroll
    for (int i = 0; i < 8; ++i) {
        base += v[i];
        g_offset[t * 8 + i + 1] = base;
        g_cursor[t * 8 + i] = 0;
    }
}

__global__ void scatter_kernel(const int* __restrict__ senders,
                               const int* __restrict__ receivers)
{
    for (int e = blockIdx.x * blockDim.x + threadIdx.x; e < N_EDGES;
         e += gridDim.x * blockDim.x) {
        const int r = receivers[e];
        const int pos = g_offset[r] + atomicAdd(&g_cursor[r], 1);
        g_ss[pos] = senders[e];
    }
}

// ---------------- per-receiver gather/accumulate (no atomics) --------------
__global__ __launch_bounds__(256) void gather_kernel(float* __restrict__ out)
{
    const int r    = blockIdx.x;
    const int tid  = threadIdx.x;
    const int warp = tid >> 5;
    const int lane = tid & 31;

    __shared__ float ks[D];
    __shared__ float buf[8][D];

    ks[tid] = g_k[(size_t)r * D + tid];
    __syncthreads();

    const float4 k0 = *(const float4*)&ks[lane * 8];
    const float4 k1 = *(const float4*)&ks[lane * 8 + 4];

    const int beg = g_offset[r];
    const int end = g_offset[r + 1];

    float4 acc0 = make_float4(0.f, 0.f, 0.f, 0.f);
    float4 acc1 = make_float4(0.f, 0.f, 0.f, 0.f);

    for (int e = beg + warp; e < end; e += 8) {
        const int s = g_ss[e];
        const float4* qs = (const float4*)&g_q[(size_t)s * D];
        const float4 q0 = qs[lane * 2], q1 = qs[lane * 2 + 1];

        float dot = q0.x * k0.x;
        dot = fmaf(q0.y, k0.y, dot);
        dot = fmaf(q0.z, k0.z, dot);
        dot = fmaf(q0.w, k0.w, dot);
        dot = fmaf(q1.x, k1.x, dot);
        dot = fmaf(q1.y, k1.y, dot);
        dot = fmaf(q1.z, k1.z, dot);
        dot = fmaf(q1.w, k1.w, dot);

        #pragma unroll
        for (int o = 16; o > 0; o >>= 1)
            dot += __shfl_xor_sync(0xffffffffu, dot, o);

        const float4* hp = (const float4*)&g_hp[(size_t)s * D];
        const float4 h0 = hp[lane * 2], h1 = hp[lane * 2 + 1];

        acc0.x = fmaf(dot, h0.x, acc0.x);
        acc0.y = fmaf(dot, h0.y, acc0.y);
        acc0.z = fmaf(dot, h0.z, acc0.z);
        acc0.w = fmaf(dot, h0.w, acc0.w);
        acc1.x = fmaf(dot, h1.x, acc1.x);
        acc1.y = fmaf(dot, h1.y, acc1.y);
        acc1.z = fmaf(dot, h1.z, acc1.z);
        acc1.w = fmaf(dot, h1.w, acc1.w);
    }

    *(float4*)&buf[warp][lane * 8]     = acc0;
    *(float4*)&buf[warp][lane * 8 + 4] = acc1;
    __syncthreads();

    float v = buf[0][tid];
    #pragma unroll
    for (int w = 1; w < 8; ++w) v += buf[w][tid];
    out[(size_t)r * D + tid] = fmaxf(v, 0.f);
}

// ---------------------------------------------------------------------------
extern "C" void kernel_launch(void* const* d_in, const int* in_sizes, int n_in,
                              void* d_out, int out_size)
{
    const float* h  = (const float*)d_in[0];
    const float* W  = (const float*)d_in[1];
    const float* Wq = (const float*)d_in[2];
    const float* bq = (const float*)d_in[3];
    const float* Wk = (const float*)d_in[4];
    const float* bk = (const float*)d_in[5];
    const int* senders   = (const int*)d_in[6];
    const int* receivers = (const int*)d_in[7];
    float* out = (float*)d_out;

    // sort chain (independent of GEMM)
    zero_counts_kernel<<<N_NODES / 256, 256>>>();
    hist_kernel<<<512, 256>>>(receivers);
    scan_kernel<<<1, 1024>>>();
    scatter_kernel<<<512, 256>>>(senders, receivers);

    // split-precision conversion
    convert_h_kernel<<<(N_NODES * D / 4) / 256, 256>>>(h);
    convert_w_kernel<<<dim3(D, 3), 256>>>(W, Wq, Wk);

    // split-bf16 HMMA projections: h_proj, q, k
    hmma_kernel<<<dim3(N_NODES / BM, 6), 256>>>(bq, bk);

    // per-receiver gather + fused ReLU
    gather_kernel<<<N_NODES, 256>>>(out);
}

// round 6
// speedup vs baseline: 1.8152x; 1.1709x over previous
#include <cuda_runtime.h>
#include <cuda_bf16.h>
#include <cstdint>

#define N_NODES 8192
#define N_EDGES 524288
#define D 256

// ---------------- scratch (__device__ globals, no allocation) --------------
__device__ float g_q [N_NODES * D];
__device__ float g_k [N_NODES * D];
__device__ float g_hp[N_NODES * D];
__device__ int   g_count [N_NODES];
__device__ int   g_cursor[N_NODES];
__device__ int   g_offset[N_NODES + 1];
__device__ int   g_ss[N_EDGES];

__device__ __nv_bfloat16 g_ahi[N_NODES * D];   // h split-hi (row-major)
__device__ __nv_bfloat16 g_alo[N_NODES * D];   // h split-lo
__device__ __nv_bfloat16 g_wthi[3 * D * D];    // W^T split-hi: [mat][n][k]
__device__ __nv_bfloat16 g_wtlo[3 * D * D];    // W^T split-lo

// ---------------- stream/event for capture fork (host-side, created once) ---
struct StreamInit {
    cudaStream_t s2;
    cudaEvent_t fork, join;
    StreamInit() {
        cudaStreamCreateWithFlags(&s2, cudaStreamNonBlocking);
        cudaEventCreateWithFlags(&fork, cudaEventDisableTiming);
        cudaEventCreateWithFlags(&join, cudaEventDisableTiming);
    }
};
static StreamInit g_si;

// ---------------- split-precision conversion -------------------------------
__global__ __launch_bounds__(256) void convert_h_kernel(const float* __restrict__ h)
{
    const int i = blockIdx.x * blockDim.x + threadIdx.x;   // one float4 each
    float4 v = ((const float4*)h)[i];
    __nv_bfloat16 h0 = __float2bfloat16(v.x);
    __nv_bfloat16 h1 = __float2bfloat16(v.y);
    __nv_bfloat16 h2 = __float2bfloat16(v.z);
    __nv_bfloat16 h3 = __float2bfloat16(v.w);
    __nv_bfloat16 l0 = __float2bfloat16(v.x - __bfloat162float(h0));
    __nv_bfloat16 l1 = __float2bfloat16(v.y - __bfloat162float(h1));
    __nv_bfloat16 l2 = __float2bfloat16(v.z - __bfloat162float(h2));
    __nv_bfloat16 l3 = __float2bfloat16(v.w - __bfloat162float(h3));
    uint2 hw, lw;
    hw.x = (uint32_t)__bfloat16_as_ushort(h0) | ((uint32_t)__bfloat16_as_ushort(h1) << 16);
    hw.y = (uint32_t)__bfloat16_as_ushort(h2) | ((uint32_t)__bfloat16_as_ushort(h3) << 16);
    lw.x = (uint32_t)__bfloat16_as_ushort(l0) | ((uint32_t)__bfloat16_as_ushort(l1) << 16);
    lw.y = (uint32_t)__bfloat16_as_ushort(l2) | ((uint32_t)__bfloat16_as_ushort(l3) << 16);
    ((uint2*)g_ahi)[i] = hw;
    ((uint2*)g_alo)[i] = lw;
}

// W [k][n] fp32 -> Wt[mat][n][k] bf16 hi/lo, via smem tile transpose.
// grid (D/32, D/32, 3), block (32, 8)
__global__ void convert_w_kernel(const float* __restrict__ W,
                                 const float* __restrict__ Wq,
                                 const float* __restrict__ Wk)
{
    __shared__ float tile[32][33];
    const int mat = blockIdx.z;
    const float* src = (mat == 0) ? W : (mat == 1) ? Wq : Wk;
    const int n0 = blockIdx.x * 32;
    const int k0 = blockIdx.y * 32;

    #pragma unroll
    for (int i = threadIdx.y; i < 32; i += 8)          // tile[ki][ni]
        tile[i][threadIdx.x] = src[(k0 + i) * D + n0 + threadIdx.x];
    __syncthreads();

    #pragma unroll
    for (int i = threadIdx.y; i < 32; i += 8) {        // write [n][k], k coalesced
        const float x = tile[threadIdx.x][i];
        __nv_bfloat16 hi = __float2bfloat16(x);
        __nv_bfloat16 lo = __float2bfloat16(x - __bfloat162float(hi));
        const size_t dst = (size_t)mat * D * D + (size_t)(n0 + i) * D + k0 + threadIdx.x;
        g_wthi[dst] = hi;
        g_wtlo[dst] = lo;
    }
}

// ---------------- split-bf16 HMMA GEMM -------------------------------------
// C = A @ B^T; acc += ahi*bhi + ahi*blo + alo*bhi (fp32 accum).
// Block tile 128x128, BK=32, register-prefetch double buffering.
#define BM 128
#define BN 128
#define BK 32
#define PAD 8
#define LDS_STRIDE (BK + PAD)

__device__ __forceinline__ void mma_bf16(float* c, const uint32_t* a, const uint32_t* b)
{
    asm volatile(
        "mma.sync.aligned.m16n8k16.row.col.f32.bf16.bf16.f32 "
        "{%0,%1,%2,%3}, {%4,%5,%6,%7}, {%8,%9}, {%0,%1,%2,%3};"
        : "+f"(c[0]), "+f"(c[1]), "+f"(c[2]), "+f"(c[3])
        : "r"(a[0]), "r"(a[1]), "r"(a[2]), "r"(a[3]), "r"(b[0]), "r"(b[1]));
}

__global__ __launch_bounds__(256) void hmma_kernel(const float* __restrict__ bq,
                                                   const float* __restrict__ bk)
{
    __shared__ __nv_bfloat16 Ahi[BM][LDS_STRIDE];
    __shared__ __nv_bfloat16 Alo[BM][LDS_STRIDE];
    __shared__ __nv_bfloat16 Bhi[BN][LDS_STRIDE];
    __shared__ __nv_bfloat16 Blo[BN][LDS_STRIDE];

    const int tid  = threadIdx.x;
    const int wid  = tid >> 5;
    const int lane = tid & 31;
    const int gid  = lane >> 2;
    const int tig  = lane & 3;

    const int wm = wid & 3;
    const int wn = wid >> 2;

    const int m0  = blockIdx.x * BM;
    const int mat = blockIdx.y >> 1;
    const int n0  = (blockIdx.y & 1) * BN;

    const __nv_bfloat16* Bh = g_wthi + mat * D * D;
    const __nv_bfloat16* Bl = g_wtlo + mat * D * D;
    float* Cout       = (mat == 0) ? g_hp : (mat == 1) ? g_q : g_k;
    const float* bias = (mat == 1) ? bq   : (mat == 2) ? bk : nullptr;

    // per-thread tile-load geometry
    const int row0 = tid >> 2,       cq0 = (tid & 3) * 8;
    const int row1 = (tid + 256) >> 2, cq1 = cq0;   // same cq pattern

    float acc[2][8][4] = {};

    uint4 pAhi[2], pAlo[2], pBhi[2], pBlo[2];

    // prefetch chunk 0
    {
        const size_t a0 = (size_t)(m0 + row0) * D + cq0;
        const size_t a1 = (size_t)(m0 + row1) * D + cq1;
        const size_t b0 = (size_t)(n0 + row0) * D + cq0;
        const size_t b1 = (size_t)(n0 + row1) * D + cq1;
        pAhi[0] = *(const uint4*)(g_ahi + a0); pAhi[1] = *(const uint4*)(g_ahi + a1);
        pAlo[0] = *(const uint4*)(g_alo + a0); pAlo[1] = *(const uint4*)(g_alo + a1);
        pBhi[0] = *(const uint4*)(Bh + b0);    pBhi[1] = *(const uint4*)(Bh + b1);
        pBlo[0] = *(const uint4*)(Bl + b0);    pBlo[1] = *(const uint4*)(Bl + b1);
    }

    for (int c = 0; c < D / BK; ++c) {
        // store prefetched chunk to smem
        *(uint4*)&Ahi[row0][cq0] = pAhi[0]; *(uint4*)&Ahi[row1][cq1] = pAhi[1];
        *(uint4*)&Alo[row0][cq0] = pAlo[0]; *(uint4*)&Alo[row1][cq1] = pAlo[1];
        *(uint4*)&Bhi[row0][cq0] = pBhi[0]; *(uint4*)&Bhi[row1][cq1] = pBhi[1];
        *(uint4*)&Blo[row0][cq0] = pBlo[0]; *(uint4*)&Blo[row1][cq1] = pBlo[1];
        __syncthreads();

        // prefetch next chunk (overlaps with MMA below)
        if (c + 1 < D / BK) {
            const int k0 = (c + 1) * BK;
            const size_t a0 = (size_t)(m0 + row0) * D + k0 + cq0;
            const size_t a1 = (size_t)(m0 + row1) * D + k0 + cq1;
            const size_t b0 = (size_t)(n0 + row0) * D + k0 + cq0;
            const size_t b1 = (size_t)(n0 + row1) * D + k0 + cq1;
            pAhi[0] = *(const uint4*)(g_ahi + a0); pAhi[1] = *(const uint4*)(g_ahi + a1);
            pAlo[0] = *(const uint4*)(g_alo + a0); pAlo[1] = *(const uint4*)(g_alo + a1);
            pBhi[0] = *(const uint4*)(Bh + b0);    pBhi[1] = *(const uint4*)(Bh + b1);
            pBlo[0] = *(const uint4*)(Bl + b0);    pBlo[1] = *(const uint4*)(Bl + b1);
        }

        #pragma unroll
        for (int ks = 0; ks < BK / 16; ++ks) {
            const int kc = ks * 16 + tig * 2;

            uint32_t ah[2][4], al[2][4], bh[8][2], bl[8][2];
            #pragma unroll
            for (int i = 0; i < 2; ++i) {
                const int r = wm * 32 + i * 16 + gid;
                ah[i][0] = *(const uint32_t*)&Ahi[r][kc];
                ah[i][1] = *(const uint32_t*)&Ahi[r + 8][kc];
                ah[i][2] = *(const uint32_t*)&Ahi[r][kc + 8];
                ah[i][3] = *(const uint32_t*)&Ahi[r + 8][kc + 8];
                al[i][0] = *(const uint32_t*)&Alo[r][kc];
                al[i][1] = *(const uint32_t*)&Alo[r + 8][kc];
                al[i][2] = *(const uint32_t*)&Alo[r][kc + 8];
                al[i][3] = *(const uint32_t*)&Alo[r + 8][kc + 8];
            }
            #pragma unroll
            for (int j = 0; j < 8; ++j) {
                const int n = wn * 64 + j * 8 + gid;
                bh[j][0] = *(const uint32_t*)&Bhi[n][kc];
                bh[j][1] = *(const uint32_t*)&Bhi[n][kc + 8];
                bl[j][0] = *(const uint32_t*)&Blo[n][kc];
                bl[j][1] = *(const uint32_t*)&Blo[n][kc + 8];
            }

            #pragma unroll
            for (int i = 0; i < 2; ++i)
                #pragma unroll
                for (int j = 0; j < 8; ++j) {
                    mma_bf16(acc[i][j], ah[i], bh[j]);
                    mma_bf16(acc[i][j], ah[i], bl[j]);
                    mma_bf16(acc[i][j], al[i], bh[j]);
                }
        }
        __syncthreads();
    }

    #pragma unroll
    for (int i = 0; i < 2; ++i) {
        const int row = m0 + wm * 32 + i * 16 + gid;
        #pragma unroll
        for (int j = 0; j < 8; ++j) {
            const int col = n0 + wn * 64 + j * 8 + tig * 2;
            float b0 = 0.f, b1 = 0.f;
            if (bias) { b0 = bias[col]; b1 = bias[col + 1]; }
            float2 v0 = make_float2(acc[i][j][0] + b0, acc[i][j][1] + b1);
            float2 v1 = make_float2(acc[i][j][2] + b0, acc[i][j][3] + b1);
            *(float2*)&Cout[(size_t)row * D + col]       = v0;
            *(float2*)&Cout[(size_t)(row + 8) * D + col] = v1;
        }
    }
}

// ---------------- counting sort by receiver --------------------------------
__global__ void zero_counts_kernel()
{
    int i = blockIdx.x * blockDim.x + threadIdx.x;
    if (i < N_NODES) g_count[i] = 0;
}

// grid 512 x 256 = 131072 threads, 4 edges each (unrolled, independent)
__global__ __launch_bounds__(256) void hist_kernel(const int* __restrict__ receivers)
{
    const int T = 131072;
    const int t = blockIdx.x * blockDim.x + threadIdx.x;
    int r[4];
    #pragma unroll
    for (int i = 0; i < 4; ++i) r[i] = receivers[t + i * T];
    #pragma unroll
    for (int i = 0; i < 4; ++i) atomicAdd(&g_count[r[i]], 1);
}

// warp-shuffle scan: 1024 threads x 8 counts
__global__ __launch_bounds__(1024) void scan_kernel()
{
    __shared__ int wsum[32];
    const int t = threadIdx.x, lane = t & 31, warp = t >> 5;
    int v[8]; int sum = 0;
    #pragma unroll
    for (int i = 0; i < 8; ++i) { v[i] = g_count[t * 8 + i]; sum += v[i]; }

    int s = sum;
    #pragma unroll
    for (int off = 1; off < 32; off <<= 1) {
        int x = __shfl_up_sync(0xffffffffu, s, off);
        if (lane >= off) s += x;
    }
    if (lane == 31) wsum[warp] = s;
    __syncthreads();
    if (warp == 0) {
        int ws = wsum[lane];
        #pragma unroll
        for (int off = 1; off < 32; off <<= 1) {
            int x = __shfl_up_sync(0xffffffffu, ws, off);
            if (lane >= off) ws += x;
        }
        wsum[lane] = ws;
    }
    __syncthreads();

    int base = s - sum + (warp ? wsum[warp - 1] : 0);
    if (t == 0) g_offset[0] = 0;
    #pragma unroll
    for (int i = 0; i < 8; ++i) {
        base += v[i];
        g_offset[t * 8 + i + 1] = base;
        g_cursor[t * 8 + i] = 0;
    }
}

// 4-way unrolled scatter: independent atomic chains in flight
__global__ __launch_bounds__(256) void scatter_kernel(const int* __restrict__ senders,
                                                      const int* __restrict__ receivers)
{
    const int T = 131072;
    const int t = blockIdx.x * blockDim.x + threadIdx.x;
    int r[4], s[4], pos[4];
    #pragma unroll
    for (int i = 0; i < 4; ++i) {
        r[i] = receivers[t + i * T];
        s[i] = senders[t + i * T];
    }
    #pragma unroll
    for (int i = 0; i < 4; ++i)
        pos[i] = g_offset[r[i]] + atomicAdd(&g_cursor[r[i]], 1);
    #pragma unroll
    for (int i = 0; i < 4; ++i)
        g_ss[pos[i]] = s[i];
}

// ---------------- per-receiver gather/accumulate (no atomics) --------------
__global__ __launch_bounds__(256) void gather_kernel(float* __restrict__ out)
{
    const int r    = blockIdx.x;
    const int tid  = threadIdx.x;
    const int warp = tid >> 5;
    const int lane = tid & 31;

    __shared__ float ks[D];
    __shared__ float buf[8][D];

    ks[tid] = g_k[(size_t)r * D + tid];
    __syncthreads();

    const float4 k0 = *(const float4*)&ks[lane * 8];
    const float4 k1 = *(const float4*)&ks[lane * 8 + 4];

    const int beg = g_offset[r];
    const int end = g_offset[r + 1];

    float4 acc0 = make_float4(0.f, 0.f, 0.f, 0.f);
    float4 acc1 = make_float4(0.f, 0.f, 0.f, 0.f);

    for (int e = beg + warp; e < end; e += 8) {
        const int s = g_ss[e];
        const float4* qs = (const float4*)&g_q[(size_t)s * D];
        const float4 q0 = qs[lane * 2], q1 = qs[lane * 2 + 1];

        float dot = q0.x * k0.x;
        dot = fmaf(q0.y, k0.y, dot);
        dot = fmaf(q0.z, k0.z, dot);
        dot = fmaf(q0.w, k0.w, dot);
        dot = fmaf(q1.x, k1.x, dot);
        dot = fmaf(q1.y, k1.y, dot);
        dot = fmaf(q1.z, k1.z, dot);
        dot = fmaf(q1.w, k1.w, dot);

        #pragma unroll
        for (int o = 16; o > 0; o >>= 1)
            dot += __shfl_xor_sync(0xffffffffu, dot, o);

        const float4* hp = (const float4*)&g_hp[(size_t)s * D];
        const float4 h0 = hp[lane * 2], h1 = hp[lane * 2 + 1];

        acc0.x = fmaf(dot, h0.x, acc0.x);
        acc0.y = fmaf(dot, h0.y, acc0.y);
        acc0.z = fmaf(dot, h0.z, acc0.z);
        acc0.w = fmaf(dot, h0.w, acc0.w);
        acc1.x = fmaf(dot, h1.x, acc1.x);
        acc1.y = fmaf(dot, h1.y, acc1.y);
        acc1.z = fmaf(dot, h1.z, acc1.z);
        acc1.w = fmaf(dot, h1.w, acc1.w);
    }

    *(float4*)&buf[warp][lane * 8]     = acc0;
    *(float4*)&buf[warp][lane * 8 + 4] = acc1;
    __syncthreads();

    float v = buf[0][tid];
    #pragma unroll
    for (int w = 1; w < 8; ++w) v += buf[w][tid];
    out[(size_t)r * D + tid] = fmaxf(v, 0.f);
}

// ---------------------------------------------------------------------------
extern "C" void kernel_launch(void* const* d_in, const int* in_sizes, int n_in,
                              void* d_out, int out_size)
{
    const float* h  = (const float*)d_in[0];
    const float* W  = (const float*)d_in[1];
    const float* Wq = (const float*)d_in[2];
    const float* bq = (const float*)d_in[3];
    const float* Wk = (const float*)d_in[4];
    const float* bk = (const float*)d_in[5];
    const int* senders   = (const int*)d_in[6];
    const int* receivers = (const int*)d_in[7];
    float* out = (float*)d_out;

    // fork: sort chain runs concurrently with convert+GEMM
    cudaEventRecord(g_si.fork, 0);
    cudaStreamWaitEvent(g_si.s2, g_si.fork, 0);

    // branch A (s2): counting sort by receiver
    zero_counts_kernel<<<N_NODES / 256, 256, 0, g_si.s2>>>();
    hist_kernel<<<512, 256, 0, g_si.s2>>>(receivers);
    scan_kernel<<<1, 1024, 0, g_si.s2>>>();
    scatter_kernel<<<512, 256, 0, g_si.s2>>>(senders, receivers);
    cudaEventRecord(g_si.join, g_si.s2);

    // branch B (main stream): split conversion + HMMA projections
    convert_h_kernel<<<(N_NODES * D / 4) / 256, 256>>>(h);
    convert_w_kernel<<<dim3(D / 32, D / 32, 3), dim3(32, 8)>>>(W, Wq, Wk);
    hmma_kernel<<<dim3(N_NODES / BM, 6), 256>>>(bq, bk);

    // join, then per-receiver gather + fused ReLU
    cudaStreamWaitEvent(0, g_si.join, 0);
    gather_kernel<<<N_NODES, 256>>>(out);
}

// round 7
// speedup vs baseline: 2.1654x; 1.1929x over previous
#include <cuda_runtime.h>
#include <cuda_bf16.h>
#include <cuda_fp16.h>
#include <cstdint>

#define N_NODES 8192
#define N_EDGES 524288
#define D 256

// ---------------- scratch (__device__ globals, no allocation) --------------
__device__ float  g_k  [N_NODES * D];     // k stays fp32 (read once per receiver)
__device__ __half g_qh [N_NODES * D];     // q  in fp16 (gathered per edge)
__device__ __half g_hph[N_NODES * D];     // hp in fp16 (gathered per edge)
__device__ int   g_count [N_NODES];
__device__ int   g_cursor[N_NODES];
__device__ int   g_offset[N_NODES + 1];
__device__ int   g_ss[N_EDGES];

__device__ __nv_bfloat16 g_ahi[N_NODES * D];   // h split-hi (row-major)
__device__ __nv_bfloat16 g_alo[N_NODES * D];   // h split-lo
__device__ __nv_bfloat16 g_wthi[3 * D * D];    // W^T split-hi: [mat][n][k]
__device__ __nv_bfloat16 g_wtlo[3 * D * D];    // W^T split-lo

// ---------------- stream/event for capture fork (host-side, created once) ---
struct StreamInit {
    cudaStream_t s2;
    cudaEvent_t fork, join;
    StreamInit() {
        cudaStreamCreateWithFlags(&s2, cudaStreamNonBlocking);
        cudaEventCreateWithFlags(&fork, cudaEventDisableTiming);
        cudaEventCreateWithFlags(&join, cudaEventDisableTiming);
    }
};
static StreamInit g_si;

// ---------------- split-precision conversion -------------------------------
__global__ __launch_bounds__(256) void convert_h_kernel(const float* __restrict__ h)
{
    const int i = blockIdx.x * blockDim.x + threadIdx.x;   // one float4 each
    float4 v = ((const float4*)h)[i];
    __nv_bfloat16 h0 = __float2bfloat16(v.x);
    __nv_bfloat16 h1 = __float2bfloat16(v.y);
    __nv_bfloat16 h2 = __float2bfloat16(v.z);
    __nv_bfloat16 h3 = __float2bfloat16(v.w);
    __nv_bfloat16 l0 = __float2bfloat16(v.x - __bfloat162float(h0));
    __nv_bfloat16 l1 = __float2bfloat16(v.y - __bfloat162float(h1));
    __nv_bfloat16 l2 = __float2bfloat16(v.z - __bfloat162float(h2));
    __nv_bfloat16 l3 = __float2bfloat16(v.w - __bfloat162float(h3));
    uint2 hw, lw;
    hw.x = (uint32_t)__bfloat16_as_ushort(h0) | ((uint32_t)__bfloat16_as_ushort(h1) << 16);
    hw.y = (uint32_t)__bfloat16_as_ushort(h2) | ((uint32_t)__bfloat16_as_ushort(h3) << 16);
    lw.x = (uint32_t)__bfloat16_as_ushort(l0) | ((uint32_t)__bfloat16_as_ushort(l1) << 16);
    lw.y = (uint32_t)__bfloat16_as_ushort(l2) | ((uint32_t)__bfloat16_as_ushort(l3) << 16);
    ((uint2*)g_ahi)[i] = hw;
    ((uint2*)g_alo)[i] = lw;
}

// W [k][n] fp32 -> Wt[mat][n][k] bf16 hi/lo via smem tile transpose.
__global__ void convert_w_kernel(const float* __restrict__ W,
                                 const float* __restrict__ Wq,
                                 const float* __restrict__ Wk)
{
    __shared__ float tile[32][33];
    const int mat = blockIdx.z;
    const float* src = (mat == 0) ? W : (mat == 1) ? Wq : Wk;
    const int n0 = blockIdx.x * 32;
    const int k0 = blockIdx.y * 32;

    #pragma unroll
    for (int i = threadIdx.y; i < 32; i += 8)
        tile[i][threadIdx.x] = src[(k0 + i) * D + n0 + threadIdx.x];
    __syncthreads();

    #pragma unroll
    for (int i = threadIdx.y; i < 32; i += 8) {
        const float x = tile[threadIdx.x][i];
        __nv_bfloat16 hi = __float2bfloat16(x);
        __nv_bfloat16 lo = __float2bfloat16(x - __bfloat162float(hi));
        const size_t dst = (size_t)mat * D * D + (size_t)(n0 + i) * D + k0 + threadIdx.x;
        g_wthi[dst] = hi;
        g_wtlo[dst] = lo;
    }
}

// ---------------- split-bf16 HMMA GEMM -------------------------------------
#define BM 128
#define BN 128
#define BK 32
#define PAD 8
#define LDS_STRIDE (BK + PAD)

__device__ __forceinline__ void mma_bf16(float* c, const uint32_t* a, const uint32_t* b)
{
    asm volatile(
        "mma.sync.aligned.m16n8k16.row.col.f32.bf16.bf16.f32 "
        "{%0,%1,%2,%3}, {%4,%5,%6,%7}, {%8,%9}, {%0,%1,%2,%3};"
        : "+f"(c[0]), "+f"(c[1]), "+f"(c[2]), "+f"(c[3])
        : "r"(a[0]), "r"(a[1]), "r"(a[2]), "r"(a[3]), "r"(b[0]), "r"(b[1]));
}

__global__ __launch_bounds__(256) void hmma_kernel(const float* __restrict__ bq,
                                                   const float* __restrict__ bk)
{
    __shared__ __nv_bfloat16 Ahi[BM][LDS_STRIDE];
    __shared__ __nv_bfloat16 Alo[BM][LDS_STRIDE];
    __shared__ __nv_bfloat16 Bhi[BN][LDS_STRIDE];
    __shared__ __nv_bfloat16 Blo[BN][LDS_STRIDE];

    const int tid  = threadIdx.x;
    const int wid  = tid >> 5;
    const int lane = tid & 31;
    const int gid  = lane >> 2;
    const int tig  = lane & 3;

    const int wm = wid & 3;
    const int wn = wid >> 2;

    const int m0  = blockIdx.x * BM;
    const int mat = blockIdx.y >> 1;
    const int n0  = (blockIdx.y & 1) * BN;

    const __nv_bfloat16* Bh = g_wthi + mat * D * D;
    const __nv_bfloat16* Bl = g_wtlo + mat * D * D;
    const float* bias = (mat == 1) ? bq : (mat == 2) ? bk : nullptr;

    const int row0 = tid >> 2,         cq0 = (tid & 3) * 8;
    const int row1 = (tid + 256) >> 2, cq1 = cq0;

    float acc[2][8][4] = {};
    uint4 pAhi[2], pAlo[2], pBhi[2], pBlo[2];

    {
        const size_t a0 = (size_t)(m0 + row0) * D + cq0;
        const size_t a1 = (size_t)(m0 + row1) * D + cq1;
        const size_t b0 = (size_t)(n0 + row0) * D + cq0;
        const size_t b1 = (size_t)(n0 + row1) * D + cq1;
        pAhi[0] = *(const uint4*)(g_ahi + a0); pAhi[1] = *(const uint4*)(g_ahi + a1);
        pAlo[0] = *(const uint4*)(g_alo + a0); pAlo[1] = *(const uint4*)(g_alo + a1);
        pBhi[0] = *(const uint4*)(Bh + b0);    pBhi[1] = *(const uint4*)(Bh + b1);
        pBlo[0] = *(const uint4*)(Bl + b0);    pBlo[1] = *(const uint4*)(Bl + b1);
    }

    for (int c = 0; c < D / BK; ++c) {
        *(uint4*)&Ahi[row0][cq0] = pAhi[0]; *(uint4*)&Ahi[row1][cq1] = pAhi[1];
        *(uint4*)&Alo[row0][cq0] = pAlo[0]; *(uint4*)&Alo[row1][cq1] = pAlo[1];
        *(uint4*)&Bhi[row0][cq0] = pBhi[0]; *(uint4*)&Bhi[row1][cq1] = pBhi[1];
        *(uint4*)&Blo[row0][cq0] = pBlo[0]; *(uint4*)&Blo[row1][cq1] = pBlo[1];
        __syncthreads();

        if (c + 1 < D / BK) {
            const int k0 = (c + 1) * BK;
            const size_t a0 = (size_t)(m0 + row0) * D + k0 + cq0;
            const size_t a1 = (size_t)(m0 + row1) * D + k0 + cq1;
            const size_t b0 = (size_t)(n0 + row0) * D + k0 + cq0;
            const size_t b1 = (size_t)(n0 + row1) * D + k0 + cq1;
            pAhi[0] = *(const uint4*)(g_ahi + a0); pAhi[1] = *(const uint4*)(g_ahi + a1);
            pAlo[0] = *(const uint4*)(g_alo + a0); pAlo[1] = *(const uint4*)(g_alo + a1);
            pBhi[0] = *(const uint4*)(Bh + b0);    pBhi[1] = *(const uint4*)(Bh + b1);
            pBlo[0] = *(const uint4*)(Bl + b0);    pBlo[1] = *(const uint4*)(Bl + b1);
        }

        #pragma unroll
        for (int ks = 0; ks < BK / 16; ++ks) {
            const int kc = ks * 16 + tig * 2;

            uint32_t ah[2][4], al[2][4], bh[8][2], bl[8][2];
            #pragma unroll
            for (int i = 0; i < 2; ++i) {
                const int r = wm * 32 + i * 16 + gid;
                ah[i][0] = *(const uint32_t*)&Ahi[r][kc];
                ah[i][1] = *(const uint32_t*)&Ahi[r + 8][kc];
                ah[i][2] = *(const uint32_t*)&Ahi[r][kc + 8];
                ah[i][3] = *(const uint32_t*)&Ahi[r + 8][kc + 8];
                al[i][0] = *(const uint32_t*)&Alo[r][kc];
                al[i][1] = *(const uint32_t*)&Alo[r + 8][kc];
                al[i][2] = *(const uint32_t*)&Alo[r][kc + 8];
                al[i][3] = *(const uint32_t*)&Alo[r + 8][kc + 8];
            }
            #pragma unroll
            for (int j = 0; j < 8; ++j) {
                const int n = wn * 64 + j * 8 + gid;
                bh[j][0] = *(const uint32_t*)&Bhi[n][kc];
                bh[j][1] = *(const uint32_t*)&Bhi[n][kc + 8];
                bl[j][0] = *(const uint32_t*)&Blo[n][kc];
                bl[j][1] = *(const uint32_t*)&Blo[n][kc + 8];
            }

            #pragma unroll
            for (int i = 0; i < 2; ++i)
                #pragma unroll
                for (int j = 0; j < 8; ++j) {
                    mma_bf16(acc[i][j], ah[i], bh[j]);
                    mma_bf16(acc[i][j], ah[i], bl[j]);
                    mma_bf16(acc[i][j], al[i], bh[j]);
                }
        }
        __syncthreads();
    }

    // ---- epilogue: hp (mat 0), q (mat 1) -> fp16; k (mat 2) -> fp32 --------
    #pragma unroll
    for (int i = 0; i < 2; ++i) {
        const int row = m0 + wm * 32 + i * 16 + gid;
        #pragma unroll
        for (int j = 0; j < 8; ++j) {
            const int col = n0 + wn * 64 + j * 8 + tig * 2;
            float b0 = 0.f, b1 = 0.f;
            if (bias) { b0 = bias[col]; b1 = bias[col + 1]; }
            const float v00 = acc[i][j][0] + b0, v01 = acc[i][j][1] + b1;
            const float v10 = acc[i][j][2] + b0, v11 = acc[i][j][3] + b1;
            if (mat == 2) {
                *(float2*)&g_k[(size_t)row * D + col]       = make_float2(v00, v01);
                *(float2*)&g_k[(size_t)(row + 8) * D + col] = make_float2(v10, v11);
            } else {
                __half* dst = (mat == 0) ? g_hph : g_qh;
                *(__half2*)&dst[(size_t)row * D + col]       = __floats2half2_rn(v00, v01);
                *(__half2*)&dst[(size_t)(row + 8) * D + col] = __floats2half2_rn(v10, v11);
            }
        }
    }
}

// ---------------- counting sort by receiver --------------------------------
__global__ void zero_counts_kernel()
{
    int i = blockIdx.x * blockDim.x + threadIdx.x;
    if (i < N_NODES) g_count[i] = 0;
}

__global__ __launch_bounds__(256) void hist_kernel(const int* __restrict__ receivers)
{
    const int T = 131072;
    const int t = blockIdx.x * blockDim.x + threadIdx.x;
    int r[4];
    #pragma unroll
    for (int i = 0; i < 4; ++i) r[i] = receivers[t + i * T];
    #pragma unroll
    for (int i = 0; i < 4; ++i) atomicAdd(&g_count[r[i]], 1);
}

__global__ __launch_bounds__(1024) void scan_kernel()
{
    __shared__ int wsum[32];
    const int t = threadIdx.x, lane = t & 31, warp = t >> 5;
    int v[8]; int sum = 0;
    #pragma unroll
    for (int i = 0; i < 8; ++i) { v[i] = g_count[t * 8 + i]; sum += v[i]; }

    int s = sum;
    #pragma unroll
    for (int off = 1; off < 32; off <<= 1) {
        int x = __shfl_up_sync(0xffffffffu, s, off);
        if (lane >= off) s += x;
    }
    if (lane == 31) wsum[warp] = s;
    __syncthreads();
    if (warp == 0) {
        int ws = wsum[lane];
        #pragma unroll
        for (int off = 1; off < 32; off <<= 1) {
            int x = __shfl_up_sync(0xffffffffu, ws, off);
            if (lane >= off) ws += x;
        }
        wsum[lane] = ws;
    }
    __syncthreads();

    int base = s - sum + (warp ? wsum[warp - 1] : 0);
    if (t == 0) g_offset[0] = 0;
    #pragma unroll
    for (int i = 0; i < 8; ++i) {
        base += v[i];
        g_offset[t * 8 + i + 1] = base;
        g_cursor[t * 8 + i] = 0;
    }
}

// 1 edge per thread: maximum concurrent atomic chains
__global__ __launch_bounds__(256) void scatter_kernel(const int* __restrict__ senders,
                                                      const int* __restrict__ receivers)
{
    const int e = blockIdx.x * blockDim.x + threadIdx.x;
    if (e < N_EDGES) {
        const int r = receivers[e];
        const int pos = g_offset[r] + atomicAdd(&g_cursor[r], 1);
        g_ss[pos] = senders[e];
    }
}

// ---------------- per-receiver gather/accumulate (fp16 gathers) ------------
__global__ __launch_bounds__(256) void gather_kernel(float* __restrict__ out)
{
    const int r    = blockIdx.x;
    const int tid  = threadIdx.x;
    const int warp = tid >> 5;
    const int lane = tid & 31;

    __shared__ float ks[D];
    __shared__ float buf[8][D];

    ks[tid] = g_k[(size_t)r * D + tid];
    __syncthreads();

    // lane owns dims [lane*8, lane*8+8)
    const float4 k0 = *(const float4*)&ks[lane * 8];
    const float4 k1 = *(const float4*)&ks[lane * 8 + 4];

    const int beg = g_offset[r];
    const int end = g_offset[r + 1];

    float4 acc0 = make_float4(0.f, 0.f, 0.f, 0.f);
    float4 acc1 = make_float4(0.f, 0.f, 0.f, 0.f);

    for (int e = beg + warp; e < end; e += 8) {
        const int s = g_ss[e];

        // q[s] fp16: 8 halves = one uint4
        const uint4 qv = *(const uint4*)&g_qh[(size_t)s * D + lane * 8];
        const float2 q0 = __half22float2(*(const __half2*)&qv.x);
        const float2 q1 = __half22float2(*(const __half2*)&qv.y);
        const float2 q2 = __half22float2(*(const __half2*)&qv.z);
        const float2 q3 = __half22float2(*(const __half2*)&qv.w);

        float dot = q0.x * k0.x;
        dot = fmaf(q0.y, k0.y, dot);
        dot = fmaf(q1.x, k0.z, dot);
        dot = fmaf(q1.y, k0.w, dot);
        dot = fmaf(q2.x, k1.x, dot);
        dot = fmaf(q2.y, k1.y, dot);
        dot = fmaf(q3.x, k1.z, dot);
        dot = fmaf(q3.y, k1.w, dot);

        #pragma unroll
        for (int o = 16; o > 0; o >>= 1)
            dot += __shfl_xor_sync(0xffffffffu, dot, o);

        // hp[s] fp16: 8 halves = one uint4
        const uint4 hv = *(const uint4*)&g_hph[(size_t)s * D + lane * 8];
        const float2 h0 = __half22float2(*(const __half2*)&hv.x);
        const float2 h1 = __half22float2(*(const __half2*)&hv.y);
        const float2 h2 = __half22float2(*(const __half2*)&hv.z);
        const float2 h3 = __half22float2(*(const __half2*)&hv.w);

        acc0.x = fmaf(dot, h0.x, acc0.x);
        acc0.y = fmaf(dot, h0.y, acc0.y);
        acc0.z = fmaf(dot, h1.x, acc0.z);
        acc0.w = fmaf(dot, h1.y, acc0.w);
        acc1.x = fmaf(dot, h2.x, acc1.x);
        acc1.y = fmaf(dot, h2.y, acc1.y);
        acc1.z = fmaf(dot, h3.x, acc1.z);
        acc1.w = fmaf(dot, h3.y, acc1.w);
    }

    *(float4*)&buf[warp][lane * 8]     = acc0;
    *(float4*)&buf[warp][lane * 8 + 4] = acc1;
    __syncthreads();

    float v = buf[0][tid];
    #pragma unroll
    for (int w = 1; w < 8; ++w) v += buf[w][tid];
    out[(size_t)r * D + tid] = fmaxf(v, 0.f);
}

// ---------------------------------------------------------------------------
extern "C" void kernel_launch(void* const* d_in, const int* in_sizes, int n_in,
                              void* d_out, int out_size)
{
    const float* h  = (const float*)d_in[0];
    const float* W  = (const float*)d_in[1];
    const float* Wq = (const float*)d_in[2];
    const float* bq = (const float*)d_in[3];
    const float* Wk = (const float*)d_in[4];
    const float* bk = (const float*)d_in[5];
    const int* senders   = (const int*)d_in[6];
    const int* receivers = (const int*)d_in[7];
    float* out = (float*)d_out;

    // fork: sort chain runs concurrently with convert+GEMM
    cudaEventRecord(g_si.fork, 0);
    cudaStreamWaitEvent(g_si.s2, g_si.fork, 0);

    // branch A (s2): counting sort by receiver
    zero_counts_kernel<<<N_NODES / 256, 256, 0, g_si.s2>>>();
    hist_kernel<<<512, 256, 0, g_si.s2>>>(receivers);
    scan_kernel<<<1, 1024, 0, g_si.s2>>>();
    scatter_kernel<<<N_EDGES / 256, 256, 0, g_si.s2>>>(senders, receivers);
    cudaEventRecord(g_si.join, g_si.s2);

    // branch B (main stream): split conversion + HMMA projections
    convert_h_kernel<<<(N_NODES * D / 4) / 256, 256>>>(h);
    convert_w_kernel<<<dim3(D / 32, D / 32, 3), dim3(32, 8)>>>(W, Wq, Wk);
    hmma_kernel<<<dim3(N_NODES / BM, 6), 256>>>(bq, bk);

    // join, then per-receiver gather + fused ReLU
    cudaStreamWaitEvent(0, g_si.join, 0);
    gather_kernel<<<N_NODES, 256>>>(out);
}